// round 6
// baseline (speedup 1.0000x reference)
#include <cuda_runtime.h>
#include <cuda_fp16.h>
#include <math.h>
#include <stdint.h>

#define N_ATOMS 100000
#define IN_F    1008
#define KPAD    1024
#define H1      256
#define H2      192
#define H3      160
#define CALPHA  0.1f
#define MT      128
#define TPB     256
#define NT_MAX  ((N_ATOMS + MT - 1) / MT)       // 782
#define PAD_MAX ((NT_MAX + 5) * MT)

// ---------------- device scratch (static, no allocations) ----------------
__device__ int g_type[N_ATOMS];
__device__ int g_sorted[PAD_MAX];               // padded, -1 filled
__device__ int g_counts[5], g_poff[5], g_cursor[5], g_is64;
// fragment-order fp16 weights: [t][kc][n8][ks][lane] as uint2
__device__ uint2 g_W16_1[5 * H1 * KPAD / 4];
__device__ uint2 g_W16_2[5 * H2 * H1 / 4];
__device__ uint2 g_W16_3[5 * H3 * H2 / 4];

// ---------------- helpers ----------------
__device__ __forceinline__ float celu_f(float x) {
    return x > 0.0f ? x : CALPHA * expm1f(x * (1.0f / CALPHA));
}
__device__ __forceinline__ uint32_t pack2(float a, float b) {
    __half2 h = __floats2half2_rn(a, b);
    return *reinterpret_cast<uint32_t*>(&h);
}
__device__ __forceinline__ void cp16(uint32_t dst, const void* src) {
    asm volatile("cp.async.cg.shared.global [%0], [%1], 16;"
                 :: "r"(dst), "l"(src) : "memory");
}
__device__ __forceinline__ void cp16z(uint32_t dst, const void* src, int valid) {
    asm volatile("cp.async.cg.shared.global [%0], [%1], 16, %2;"
                 :: "r"(dst), "l"(src), "r"(valid ? 16 : 0) : "memory");
}
#define CP_COMMIT() asm volatile("cp.async.commit_group;" ::: "memory")
#define CP_WAIT1()  asm volatile("cp.async.wait_group 1;" ::: "memory")
#define CP_WAIT0()  asm volatile("cp.async.wait_group 0;" ::: "memory")

#define MMA16(d, a, b0, b1) \
    asm volatile("mma.sync.aligned.m16n8k16.row.col.f32.f16.f16.f32 " \
                 "{%0,%1,%2,%3},{%4,%5,%6,%7},{%8,%9},{%0,%1,%2,%3};" \
                 : "+f"((d)[0]), "+f"((d)[1]), "+f"((d)[2]), "+f"((d)[3]) \
                 : "r"((a).x), "r"((a).y), "r"((a).z), "r"((a).w), \
                   "r"(b0), "r"(b1))

// ---------------- plumbing kernels ----------------
__global__ void k_init(const int* __restrict__ z32, float* out, int n_out) {
    int i = blockIdx.x * blockDim.x + threadIdx.x;
    if (i < n_out) out[i] = 0.0f;
    if (i < PAD_MAX) g_sorted[i] = -1;
    if (i == 0) {
        g_is64 = (z32[1] == 0 && z32[3] == 0 && z32[5] == 0 && z32[7] == 0) ? 1 : 0;
        for (int t = 0; t < 5; t++) { g_counts[t] = 0; g_cursor[t] = 0; }
    }
}
__device__ __forceinline__ int z_to_type(int zv) {
    return (zv == 1) ? 0 : (zv == 6) ? 1 : (zv == 7) ? 2 : (zv == 8) ? 3 : 4;
}
__global__ void k_count(const int* __restrict__ z32) {
    int i = blockIdx.x * blockDim.x + threadIdx.x;
    if (i >= N_ATOMS) return;
    int zv = g_is64 ? z32[2 * i] : z32[i];
    int t = z_to_type(zv);
    g_type[i] = t;
    atomicAdd(&g_counts[t], 1);
}
__global__ void k_scan() {
    if (threadIdx.x == 0 && blockIdx.x == 0) {
        int acc = 0;
        for (int t = 0; t < 5; t++) {
            g_poff[t] = acc;
            acc += ((g_counts[t] + MT - 1) / MT) * MT;
        }
    }
}
__global__ void k_scatter() {
    int i = blockIdx.x * blockDim.x + threadIdx.x;
    if (i >= N_ATOMS) return;
    int t = g_type[i];
    int pos = g_poff[t] + atomicAdd(&g_cursor[t], 1);
    g_sorted[pos] = i;
}

// weight permute into fragment order, fp16
__device__ __forceinline__ void prep_w(uint2* dst, const float* src,
                                       int NN, int KTOT, int KIN, int i) {
    const int lane = i & 31;
    const int ks   = (i >> 5) & 3;
    int rest = i >> 7;
    const int n8 = rest % (NN / 8); rest /= (NN / 8);
    const int kc = rest % (KTOT / 64);
    const int t  = rest / (KTOT / 64);
    const int n = n8 * 8 + (lane >> 2);
    const int k0 = kc * 64 + ks * 16 + 2 * (lane & 3);
    const int k1 = k0 + 8;
    const float* W = src + (size_t)t * KIN * NN;
    float v00 = (k0 < KIN)     ? W[(size_t)k0 * NN + n]       : 0.0f;
    float v01 = (k0 + 1 < KIN) ? W[(size_t)(k0 + 1) * NN + n] : 0.0f;
    float v10 = (k1 < KIN)     ? W[(size_t)k1 * NN + n]       : 0.0f;
    float v11 = (k1 + 1 < KIN) ? W[(size_t)(k1 + 1) * NN + n] : 0.0f;
    dst[i] = make_uint2(pack2(v00, v01), pack2(v10, v11));
}
__global__ void k_prep(const float* __restrict__ W1, const float* __restrict__ W2,
                       const float* __restrict__ W3) {
    int i = blockIdx.x * blockDim.x + threadIdx.x;
    const int n1 = 5 * H1 * KPAD / 4, n2 = 5 * H2 * H1 / 4, n3 = 5 * H3 * H2 / 4;
    if (i < n1) prep_w(g_W16_1, W1, H1, KPAD, IN_F, i);
    else if (i < n1 + n2) prep_w(g_W16_2, W2, H2, H1, H1, i - n1);
    else if (i < n1 + n2 + n3) prep_w(g_W16_3, W3, H3, H2, H2, i - n1 - n2);
}

// ---------------- SMEM layout ----------------
#define A_STR  72                       // fp32 A row stride (floats)
#define SM_A   0                        // 2*128*72*4 = 73728
#define SM_B   73728                    // 2*2048 uint4 = 65536
#define SM_H   139264                   // 4096 uint4 = 65536
#define SM_IDS 204800                   // 128 ints
#define SM_TOTAL 205376

// ---------------- fully fused kernel ----------------
// 256 threads = 8 warps as 2(M) x 4(N). One 128-atom tile does all 4 layers.
__global__ void __launch_bounds__(TPB)
k_fused(const float* __restrict__ feat,
        const int*   __restrict__ batch32,
        const float* __restrict__ b1, const float* __restrict__ b2,
        const float* __restrict__ b3, const float* __restrict__ W4,
        const float* __restrict__ b4,
        float* __restrict__ out)
{
    const int t = blockIdx.y;
    const int cnt = g_counts[t];
    const int start = blockIdx.x * MT;
    if (start >= cnt) return;
    const int nact = min(MT, cnt - start);
    const int tile0 = g_poff[t] + start;

    extern __shared__ __align__(16) char smem[];
    float* sA  = reinterpret_cast<float*>(smem + SM_A);
    uint4* sB4 = reinterpret_cast<uint4*>(smem + SM_B);
    uint2* sB2 = reinterpret_cast<uint2*>(smem + SM_B);
    uint4* sH  = reinterpret_cast<uint4*>(smem + SM_H);    // h1 then h2 fragments? h1 here
    uint4* sH2 = reinterpret_cast<uint4*>(smem + SM_A);    // h2 fragments reuse A region
    int*   sids = reinterpret_cast<int*>(smem + SM_IDS);

    const int tid = threadIdx.x;
    const int wid = tid >> 5, lane = tid & 31;
    const int wm = wid & 1, wn = wid >> 1;
    const int g = lane >> 2, tig = lane & 3;

    if (tid < MT) sids[tid] = g_sorted[tile0 + tid];
    __syncthreads();

    const uint32_t sA_u = (uint32_t)__cvta_generic_to_shared(sA);
    const uint32_t sB_u = (uint32_t)__cvta_generic_to_shared(sB4);

    // ================= Layer 1: K=1024 (16 chunks of 64), NN=256 =================
    {
        constexpr int NCH = 16, NT8 = 8;
        const uint4* Bt = reinterpret_cast<const uint4*>(g_W16_1)
                          + (size_t)t * (H1 * KPAD / 8);

        float acc[4][NT8][4];
#pragma unroll
        for (int i = 0; i < 4; i++)
#pragma unroll
            for (int j = 0; j < NT8; j++)
#pragma unroll
                for (int q = 0; q < 4; q++) acc[i][j][q] = 0.0f;

        auto issue = [&](int c) {
            const int s = c & 1;
            // A: 128 rows x 64 fp32 (gather by id, zero-fill pads/tail)
#pragma unroll
            for (int q = tid; q < MT * 16; q += TPB) {
                const int r = q >> 4, fq = q & 15;
                const int id = sids[r];
                const int k = c * 64 + fq * 4;
                const int v = (id >= 0) && (k < IN_F);
                const float* src = feat + (v ? ((size_t)id * IN_F + k) : 0);
                cp16z(sA_u + (((s * MT + r) * A_STR + fq * 4) << 2), src, v);
            }
            // B: 2048 uint4 fragment-order
            const uint4* b = Bt + (size_t)c * 2048;
#pragma unroll
            for (int q = tid; q < 2048; q += TPB)
                cp16(sB_u + ((s * 2048 + q) << 4), b + q);
            CP_COMMIT();
        };

        issue(0);
        for (int c = 0; c < NCH; c++) {
            if (c + 1 < NCH) { issue(c + 1); CP_WAIT1(); }
            else             { CP_WAIT0(); }
            __syncthreads();
            const float* A = sA + (c & 1) * MT * A_STR;
            const uint2* B = sB2 + (c & 1) * 4096;
#pragma unroll
            for (int ksl = 0; ksl < 4; ksl++) {
                const int k0 = ksl * 16 + 2 * tig;
                uint4 av[4];
#pragma unroll
                for (int mt = 0; mt < 4; mt++) {
                    const int r0 = wm * 64 + mt * 16 + g;
                    float2 p0 = *reinterpret_cast<const float2*>(A + r0 * A_STR + k0);
                    float2 p1 = *reinterpret_cast<const float2*>(A + (r0 + 8) * A_STR + k0);
                    float2 p2 = *reinterpret_cast<const float2*>(A + r0 * A_STR + k0 + 8);
                    float2 p3 = *reinterpret_cast<const float2*>(A + (r0 + 8) * A_STR + k0 + 8);
                    av[mt].x = pack2(p0.x, p0.y);
                    av[mt].y = pack2(p1.x, p1.y);
                    av[mt].z = pack2(p2.x, p2.y);
                    av[mt].w = pack2(p3.x, p3.y);
                }
#pragma unroll
                for (int nt = 0; nt < NT8; nt++) {
                    const uint2 bv = B[((wn * NT8 + nt) * 4 + ksl) * 32 + lane];
#pragma unroll
                    for (int mt = 0; mt < 4; mt++) MMA16(acc[mt][nt], av[mt], bv.x, bv.y);
                }
            }
            __syncthreads();
        }

        // epilogue 1: bias+celu -> fp16 fragments in sH (h1: 16 ks x 8 bm x 32)
        const float* bv = b1 + t * H1;
#pragma unroll
        for (int mt = 0; mt < 4; mt++) {
#pragma unroll
            for (int ntp = 0; ntp < NT8 / 2; ntp++) {
                const int nt = 2 * ntp;
                const int c0 = wn * (H1 / 4) + nt * 8 + 2 * tig;
                const int c1 = c0 + 8;
                const float bb0 = __ldg(bv + c0), bb1 = __ldg(bv + c0 + 1);
                const float bb2 = __ldg(bv + c1), bb3 = __ldg(bv + c1 + 1);
                uint4 v;
                v.x = pack2(celu_f(acc[mt][nt][0] + bb0),     celu_f(acc[mt][nt][1] + bb1));
                v.y = pack2(celu_f(acc[mt][nt][2] + bb0),     celu_f(acc[mt][nt][3] + bb1));
                v.z = pack2(celu_f(acc[mt][nt + 1][0] + bb2), celu_f(acc[mt][nt + 1][1] + bb3));
                v.w = pack2(celu_f(acc[mt][nt + 1][2] + bb2), celu_f(acc[mt][nt + 1][3] + bb3));
                const int ks = wn * (NT8 / 2) + ntp;
                sH[(ks * 8 + wm * 4 + mt) * 32 + lane] = v;
            }
        }
    }
    __syncthreads();

    // ================= Layer 2: K=256 (4 chunks), NN=192 =================
    {
        constexpr int NCH = 4, NT8 = 6, BCH = H2 * 8;   // 1536 uint4/chunk
        const uint4* Bt = reinterpret_cast<const uint4*>(g_W16_2)
                          + (size_t)t * (H2 * H1 / 8);

        float acc[4][NT8][4];
#pragma unroll
        for (int i = 0; i < 4; i++)
#pragma unroll
            for (int j = 0; j < NT8; j++)
#pragma unroll
                for (int q = 0; q < 4; q++) acc[i][j][q] = 0.0f;

        auto issueB = [&](int c) {
            const uint4* b = Bt + (size_t)c * BCH;
#pragma unroll
            for (int q = tid; q < BCH; q += TPB)
                cp16(sB_u + ((( c & 1) * 2048 + q) << 4), b + q);
            CP_COMMIT();
        };

        issueB(0);
        for (int c = 0; c < NCH; c++) {
            if (c + 1 < NCH) { issueB(c + 1); CP_WAIT1(); }
            else             { CP_WAIT0(); }
            __syncthreads();
            const uint2* B = sB2 + (c & 1) * 4096;
#pragma unroll
            for (int ksl = 0; ksl < 4; ksl++) {
                uint4 av[4];
#pragma unroll
                for (int mt = 0; mt < 4; mt++)
                    av[mt] = sH[((c * 4 + ksl) * 8 + wm * 4 + mt) * 32 + lane];
#pragma unroll
                for (int nt = 0; nt < NT8; nt++) {
                    const uint2 bv = B[((wn * NT8 + nt) * 4 + ksl) * 32 + lane];
#pragma unroll
                    for (int mt = 0; mt < 4; mt++) MMA16(acc[mt][nt], av[mt], bv.x, bv.y);
                }
            }
            __syncthreads();
        }

        // epilogue 2: h2 fragments (12 ks x 8 bm x 32) into sH2 (old A region)
        const float* bv = b2 + t * H2;
#pragma unroll
        for (int mt = 0; mt < 4; mt++) {
#pragma unroll
            for (int ntp = 0; ntp < NT8 / 2; ntp++) {
                const int nt = 2 * ntp;
                const int c0 = wn * (H2 / 4) + nt * 8 + 2 * tig;
                const int c1 = c0 + 8;
                const float bb0 = __ldg(bv + c0), bb1 = __ldg(bv + c0 + 1);
                const float bb2 = __ldg(bv + c1), bb3 = __ldg(bv + c1 + 1);
                uint4 v;
                v.x = pack2(celu_f(acc[mt][nt][0] + bb0),     celu_f(acc[mt][nt][1] + bb1));
                v.y = pack2(celu_f(acc[mt][nt][2] + bb0),     celu_f(acc[mt][nt][3] + bb1));
                v.z = pack2(celu_f(acc[mt][nt + 1][0] + bb2), celu_f(acc[mt][nt + 1][1] + bb3));
                v.w = pack2(celu_f(acc[mt][nt + 1][2] + bb2), celu_f(acc[mt][nt + 1][3] + bb3));
                const int ks = wn * (NT8 / 2) + ntp;
                sH2[(ks * 8 + wm * 4 + mt) * 32 + lane] = v;
            }
        }
    }
    __syncthreads();

    // ================= Layer 3: K=192 (3 chunks), NN=160 + layer 4 =================
    {
        constexpr int NCH = 3, NT8 = 5, BCH = H3 * 8;   // 1280 uint4/chunk
        const uint4* Bt = reinterpret_cast<const uint4*>(g_W16_3)
                          + (size_t)t * (H3 * H2 / 8);

        float acc[4][NT8][4];
#pragma unroll
        for (int i = 0; i < 4; i++)
#pragma unroll
            for (int j = 0; j < NT8; j++)
#pragma unroll
                for (int q = 0; q < 4; q++) acc[i][j][q] = 0.0f;

        auto issueB = [&](int c) {
            const uint4* b = Bt + (size_t)c * BCH;
#pragma unroll
            for (int q = tid; q < BCH; q += TPB)
                cp16(sB_u + (((c & 1) * 2048 + q) << 4), b + q);
            CP_COMMIT();
        };

        issueB(0);
        for (int c = 0; c < NCH; c++) {
            if (c + 1 < NCH) { issueB(c + 1); CP_WAIT1(); }
            else             { CP_WAIT0(); }
            __syncthreads();
            const uint2* B = sB2 + (c & 1) * 4096;
#pragma unroll
            for (int ksl = 0; ksl < 4; ksl++) {
                uint4 av[4];
#pragma unroll
                for (int mt = 0; mt < 4; mt++)
                    av[mt] = sH2[((c * 4 + ksl) * 8 + wm * 4 + mt) * 32 + lane];
#pragma unroll
                for (int nt = 0; nt < NT8; nt++) {
                    const uint2 bv = B[((wn * NT8 + nt) * 4 + ksl) * 32 + lane];
#pragma unroll
                    for (int mt = 0; mt < 4; mt++) MMA16(acc[mt][nt], av[mt], bv.x, bv.y);
                }
            }
            __syncthreads();
        }

        // epilogue 3 + layer 4: celu * W4 dot + segment sum
        float part[4][2];
#pragma unroll
        for (int mt = 0; mt < 4; mt++) { part[mt][0] = 0.0f; part[mt][1] = 0.0f; }
        const float* b3v = b3 + t * H3;
        const float* w4v = W4 + t * H3;
#pragma unroll
        for (int nt = 0; nt < NT8; nt++) {
            const int c0 = wn * (H3 / 4) + nt * 8 + 2 * tig;
            const float bb0 = __ldg(b3v + c0), bb1 = __ldg(b3v + c0 + 1);
            const float w0  = __ldg(w4v + c0), w1  = __ldg(w4v + c0 + 1);
#pragma unroll
            for (int mt = 0; mt < 4; mt++) {
                part[mt][0] += celu_f(acc[mt][nt][0] + bb0) * w0
                             + celu_f(acc[mt][nt][1] + bb1) * w1;
                part[mt][1] += celu_f(acc[mt][nt][2] + bb0) * w0
                             + celu_f(acc[mt][nt][3] + bb1) * w1;
            }
        }
#pragma unroll
        for (int mt = 0; mt < 4; mt++)
#pragma unroll
            for (int rh = 0; rh < 2; rh++) {
                part[mt][rh] += __shfl_xor_sync(0xffffffffu, part[mt][rh], 1);
                part[mt][rh] += __shfl_xor_sync(0xffffffffu, part[mt][rh], 2);
            }
        if (tig == 0) {
            const float b4v = __ldg(b4 + t);
#pragma unroll
            for (int mt = 0; mt < 4; mt++)
#pragma unroll
                for (int rh = 0; rh < 2; rh++) {
                    const int row = wm * 64 + mt * 16 + rh * 8 + g;
                    if (row < nact) {
                        const int id = sids[row];
                        const int mol = g_is64 ? batch32[2 * id] : batch32[id];
                        atomicAdd(&out[mol], part[mt][rh] + (wn == 0 ? b4v : 0.0f));
                    }
                }
        }
    }
}

// ---------------- launch ----------------
extern "C" void kernel_launch(void* const* d_in, const int* in_sizes, int n_in,
                              void* d_out, int out_size) {
    const int*   z     = (const int*)  d_in[0];
    const float* feat  = (const float*)d_in[1];
    const int*   batch = (const int*)  d_in[2];
    const float* W1 = (const float*)d_in[4];
    const float* b1 = (const float*)d_in[5];
    const float* W2 = (const float*)d_in[6];
    const float* b2 = (const float*)d_in[7];
    const float* W3 = (const float*)d_in[8];
    const float* b3 = (const float*)d_in[9];
    const float* W4 = (const float*)d_in[10];
    const float* b4 = (const float*)d_in[11];
    float* out = (float*)d_out;

    cudaFuncSetAttribute(k_fused, cudaFuncAttributeMaxDynamicSharedMemorySize, SM_TOTAL);

    const int initN = (out_size > PAD_MAX) ? out_size : PAD_MAX;
    k_init<<<(initN + 255) / 256, 256>>>(z, out, out_size);
    k_count<<<(N_ATOMS + 255) / 256, 256>>>(z);
    k_scan<<<1, 1>>>();
    k_scatter<<<(N_ATOMS + 255) / 256, 256>>>();
    const int prepN = 5 * H1 * KPAD / 4 + 5 * H2 * H1 / 4 + 5 * H3 * H2 / 4;
    k_prep<<<(prepN + 255) / 256, 256>>>(W1, W2, W3);

    dim3 grid(NT_MAX, 5);
    k_fused<<<grid, TPB, SM_TOTAL>>>(feat, batch, b1, b2, b3, W4, b4, out);
}

// round 7
// speedup vs baseline: 1.4318x; 1.4318x over previous
#include <cuda_runtime.h>
#include <cuda_fp16.h>
#include <math.h>
#include <stdint.h>

#define N_ATOMS 100000
#define IN_F    1008
#define KPAD    1024
#define H1      256
#define H2      192
#define H3      160
#define CALPHA  0.1f
#define MT      128
#define TPB     512
#define NT_MAX  ((N_ATOMS + MT - 1) / MT)       // 782
#define PAD_MAX ((NT_MAX + 5) * MT)

// ---------------- device scratch (static, no allocations) ----------------
__device__ int g_type[N_ATOMS];
__device__ int g_sorted[PAD_MAX];
__device__ int g_counts[5], g_poff[5], g_cursor[5], g_is64;
// fp16 fragment-order weights
__device__ uint2 g_W16_1[5 * H1 * KPAD / 4];    // KC=32: [t][kc32][n8][ks2][lane]
__device__ uint2 g_W16_2[5 * H2 * H1 / 4];      // KC=64: [t][kc][n8][ks4][lane]
__device__ uint2 g_W16_3[5 * H3 * H2 / 4];
// fp16 fragment-order activations [tile][ks][bm(8)][lane(32)]
__device__ uint4 g_H1f[(size_t)(NT_MAX + 5) * 16 * 8 * 32];
__device__ uint4 g_H2f[(size_t)(NT_MAX + 5) * 12 * 8 * 32];

// ---------------- helpers ----------------
__device__ __forceinline__ float celu_f(float x) {
    return x > 0.0f ? x : CALPHA * expm1f(x * (1.0f / CALPHA));
}
__device__ __forceinline__ uint32_t pack2(float a, float b) {
    __half2 h = __floats2half2_rn(a, b);
    return *reinterpret_cast<uint32_t*>(&h);
}
__device__ __forceinline__ void cp16(uint32_t dst, const void* src) {
    asm volatile("cp.async.cg.shared.global [%0], [%1], 16;"
                 :: "r"(dst), "l"(src) : "memory");
}
__device__ __forceinline__ void cp16z(uint32_t dst, const void* src, int valid) {
    asm volatile("cp.async.cg.shared.global [%0], [%1], 16, %2;"
                 :: "r"(dst), "l"(src), "r"(valid ? 16 : 0) : "memory");
}
#define CP_COMMIT() asm volatile("cp.async.commit_group;" ::: "memory")
#define CP_WAIT1()  asm volatile("cp.async.wait_group 1;" ::: "memory")
#define CP_WAIT0()  asm volatile("cp.async.wait_group 0;" ::: "memory")

#define MMA16(d, a, b0, b1) \
    asm volatile("mma.sync.aligned.m16n8k16.row.col.f32.f16.f16.f32 " \
                 "{%0,%1,%2,%3},{%4,%5,%6,%7},{%8,%9},{%0,%1,%2,%3};" \
                 : "+f"((d)[0]), "+f"((d)[1]), "+f"((d)[2]), "+f"((d)[3]) \
                 : "r"((a).x), "r"((a).y), "r"((a).z), "r"((a).w), \
                   "r"(b0), "r"(b1))

// ---------------- plumbing kernels ----------------
__global__ void k_init(const int* __restrict__ z32, float* out, int n_out) {
    int i = blockIdx.x * blockDim.x + threadIdx.x;
    if (i < n_out) out[i] = 0.0f;
    if (i < PAD_MAX) g_sorted[i] = -1;
    if (i == 0) {
        g_is64 = (z32[1] == 0 && z32[3] == 0 && z32[5] == 0 && z32[7] == 0) ? 1 : 0;
        for (int t = 0; t < 5; t++) { g_counts[t] = 0; g_cursor[t] = 0; }
    }
}
__device__ __forceinline__ int z_to_type(int zv) {
    return (zv == 1) ? 0 : (zv == 6) ? 1 : (zv == 7) ? 2 : (zv == 8) ? 3 : 4;
}
__global__ void k_count(const int* __restrict__ z32) {
    int i = blockIdx.x * blockDim.x + threadIdx.x;
    if (i >= N_ATOMS) return;
    int zv = g_is64 ? z32[2 * i] : z32[i];
    int t = z_to_type(zv);
    g_type[i] = t;
    atomicAdd(&g_counts[t], 1);
}
__global__ void k_scan() {
    if (threadIdx.x == 0 && blockIdx.x == 0) {
        int acc = 0;
        for (int t = 0; t < 5; t++) {
            g_poff[t] = acc;
            acc += ((g_counts[t] + MT - 1) / MT) * MT;
        }
    }
}
__global__ void k_scatter() {
    int i = blockIdx.x * blockDim.x + threadIdx.x;
    if (i >= N_ATOMS) return;
    int t = g_type[i];
    int pos = g_poff[t] + atomicAdd(&g_cursor[t], 1);
    g_sorted[pos] = i;
}

// weight permute into fragment order, fp16. KC = k-chunk size.
template<int KC>
__device__ __forceinline__ void prep_w(uint2* dst, const float* src,
                                       int NN, int KTOT, int KIN, int i) {
    constexpr int KS = KC / 16;
    const int lane = i & 31;
    const int ks   = (i >> 5) % KS;
    int rest = i / (32 * KS);
    const int n8 = rest % (NN / 8); rest /= (NN / 8);
    const int kc = rest % (KTOT / KC);
    const int t  = rest / (KTOT / KC);
    const int n = n8 * 8 + (lane >> 2);
    const int k0 = kc * KC + ks * 16 + 2 * (lane & 3);
    const int k1 = k0 + 8;
    const float* W = src + (size_t)t * KIN * NN;
    float v00 = (k0 < KIN)     ? W[(size_t)k0 * NN + n]       : 0.0f;
    float v01 = (k0 + 1 < KIN) ? W[(size_t)(k0 + 1) * NN + n] : 0.0f;
    float v10 = (k1 < KIN)     ? W[(size_t)k1 * NN + n]       : 0.0f;
    float v11 = (k1 + 1 < KIN) ? W[(size_t)(k1 + 1) * NN + n] : 0.0f;
    dst[i] = make_uint2(pack2(v00, v01), pack2(v10, v11));
}
__global__ void k_prep(const float* __restrict__ W1, const float* __restrict__ W2,
                       const float* __restrict__ W3) {
    int i = blockIdx.x * blockDim.x + threadIdx.x;
    const int n1 = 5 * H1 * KPAD / 4, n2 = 5 * H2 * H1 / 4, n3 = 5 * H3 * H2 / 4;
    if (i < n1) prep_w<32>(g_W16_1, W1, H1, KPAD, IN_F, i);
    else if (i < n1 + n2) prep_w<64>(g_W16_2, W2, H2, H1, H1, i - n1);
    else if (i < n1 + n2 + n3) prep_w<64>(g_W16_3, W3, H3, H2, H2, i - n1 - n2);
}

// ================= GEMM 1: fp32 features -> h1 fp16 fragments =================
// 512 threads = 16 warps as 4(M) x 4(N); warp tile 32 x 64; K-chunks of 32.
#define A_STR 36
#define G1_SM_A   0                      // 2*128*36*4 = 36864
#define G1_SM_B   36864                  // 2*1024 uint4 = 32768
#define G1_SM_IDS 69632                  // 128 ints
#define G1_SM_TOTAL 70144

__global__ void __launch_bounds__(TPB)
k_gemm1(const float* __restrict__ feat, const float* __restrict__ b1)
{
    constexpr int NCH = KPAD / 32;        // 32
    constexpr int NT8 = 8;

    const int t = blockIdx.y;
    const int cnt = g_counts[t];
    const int start = blockIdx.x * MT;
    if (start >= cnt) return;
    const int tile = (g_poff[t] >> 7) + blockIdx.x;

    extern __shared__ __align__(16) char smem[];
    float* sA  = reinterpret_cast<float*>(smem + G1_SM_A);
    uint4* sB4 = reinterpret_cast<uint4*>(smem + G1_SM_B);
    uint2* sB2 = reinterpret_cast<uint2*>(smem + G1_SM_B);
    int*   sids = reinterpret_cast<int*>(smem + G1_SM_IDS);

    const int tid = threadIdx.x;
    const int wid = tid >> 5, lane = tid & 31;
    const int wm = wid & 3, wn = wid >> 2;
    const int g = lane >> 2, tig = lane & 3;

    if (tid < MT) sids[tid] = g_sorted[tile * MT + tid];
    __syncthreads();

    const uint32_t sA_u = (uint32_t)__cvta_generic_to_shared(sA);
    const uint32_t sB_u = (uint32_t)__cvta_generic_to_shared(sB4);
    const uint4* Bt = reinterpret_cast<const uint4*>(g_W16_1) + (size_t)t * (H1 * KPAD / 8);

    float acc[2][NT8][4];
#pragma unroll
    for (int i = 0; i < 2; i++)
#pragma unroll
        for (int j = 0; j < NT8; j++)
#pragma unroll
            for (int q = 0; q < 4; q++) acc[i][j][q] = 0.0f;

    auto issue = [&](int c) {
        const int s = c & 1;
        // A: 128 rows x 32 fp32
#pragma unroll
        for (int q = tid; q < MT * 8; q += TPB) {
            const int r = q >> 3, fq = q & 7;
            const int id = sids[r];
            const int k = c * 32 + fq * 4;
            const int v = (id >= 0) && (k < IN_F);
            const float* src = feat + (v ? ((size_t)id * IN_F + k) : 0);
            cp16z(sA_u + (((s * MT + r) * A_STR + fq * 4) << 2), src, v);
        }
        // B: 1024 uint4
        const uint4* b = Bt + (size_t)c * 1024;
#pragma unroll
        for (int q = tid; q < 1024; q += TPB)
            cp16(sB_u + ((s * 1024 + q) << 4), b + q);
        CP_COMMIT();
    };

    issue(0);
    for (int c = 0; c < NCH; c++) {
        if (c + 1 < NCH) { issue(c + 1); CP_WAIT1(); }
        else             { CP_WAIT0(); }
        __syncthreads();
        const float* A = sA + (c & 1) * MT * A_STR;
        const uint2* B = sB2 + (c & 1) * 2048;
#pragma unroll
        for (int ksl = 0; ksl < 2; ksl++) {
            const int k0 = ksl * 16 + 2 * tig;
            uint4 av[2];
#pragma unroll
            for (int mt = 0; mt < 2; mt++) {
                const int r0 = wm * 32 + mt * 16 + g;
                float2 p0 = *reinterpret_cast<const float2*>(A + r0 * A_STR + k0);
                float2 p1 = *reinterpret_cast<const float2*>(A + (r0 + 8) * A_STR + k0);
                float2 p2 = *reinterpret_cast<const float2*>(A + r0 * A_STR + k0 + 8);
                float2 p3 = *reinterpret_cast<const float2*>(A + (r0 + 8) * A_STR + k0 + 8);
                av[mt].x = pack2(p0.x, p0.y);
                av[mt].y = pack2(p1.x, p1.y);
                av[mt].z = pack2(p2.x, p2.y);
                av[mt].w = pack2(p3.x, p3.y);
            }
#pragma unroll
            for (int nt = 0; nt < NT8; nt++) {
                const uint2 bv = B[((wn * NT8 + nt) * 2 + ksl) * 32 + lane];
#pragma unroll
                for (int mt = 0; mt < 2; mt++) MMA16(acc[mt][nt], av[mt], bv.x, bv.y);
            }
        }
        __syncthreads();
    }

    // epilogue: bias+celu -> h1 fragments [ks16][bm8][lane32]
    uint4* Hout = g_H1f + (size_t)tile * 16 * 256;
    const float* bv = b1 + t * H1;
#pragma unroll
    for (int mt = 0; mt < 2; mt++) {
#pragma unroll
        for (int ntp = 0; ntp < NT8 / 2; ntp++) {
            const int nt = 2 * ntp;
            const int c0 = wn * 64 + nt * 8 + 2 * tig;
            const int c1 = c0 + 8;
            const float bb0 = __ldg(bv + c0), bb1 = __ldg(bv + c0 + 1);
            const float bb2 = __ldg(bv + c1), bb3 = __ldg(bv + c1 + 1);
            uint4 v;
            v.x = pack2(celu_f(acc[mt][nt][0] + bb0),     celu_f(acc[mt][nt][1] + bb1));
            v.y = pack2(celu_f(acc[mt][nt][2] + bb0),     celu_f(acc[mt][nt][3] + bb1));
            v.z = pack2(celu_f(acc[mt][nt + 1][0] + bb2), celu_f(acc[mt][nt + 1][1] + bb3));
            v.w = pack2(celu_f(acc[mt][nt + 1][2] + bb2), celu_f(acc[mt][nt + 1][3] + bb3));
            const int ks = wn * 4 + ntp;
            const int bm = wm * 2 + mt;
            Hout[(ks * 8 + bm) * 32 + lane] = v;
        }
    }
}

// ================= GEMM 2/3: fp16 fragment A =================
// 512 threads = 16 warps as 4(M) x 4(N); warp tile 32 x (NN/4); K-chunks of 64.
template<int MODE>   // 2 or 3
__global__ void __launch_bounds__(TPB)
k_gemm(const int* __restrict__ batch32,
       const float* __restrict__ bias,
       const float* __restrict__ W4,
       const float* __restrict__ b4,
       float* __restrict__ out)
{
    constexpr int NN   = (MODE == 2) ? H2 : H3;
    constexpr int KTOT = (MODE == 2) ? H1 : H2;
    constexpr int NCH  = KTOT / 64;        // 4 / 3
    constexpr int NT8  = NN / 32;          // 6 / 5
    constexpr int BCH  = NN * 8;           // uint4 per B chunk

    const int t = blockIdx.y;
    const int cnt = g_counts[t];
    const int start = blockIdx.x * MT;
    if (start >= cnt) return;
    const int nact = min(MT, cnt - start);
    const int tile = (g_poff[t] >> 7) + blockIdx.x;

    extern __shared__ __align__(16) uint4 smem4[];
    uint4* sA = smem4;                                   // [2][1024]
    uint4* sB4 = smem4 + 2048;                           // [2][BCH]
    uint2* sB2 = reinterpret_cast<uint2*>(sB4);
    int*   sids = reinterpret_cast<int*>(sB4 + 2 * BCH);

    const int tid = threadIdx.x;
    const int wid = tid >> 5, lane = tid & 31;
    const int wm = wid & 3, wn = wid >> 2;
    const int g = lane >> 2, tig = lane & 3;

    if (MODE == 3 && tid < MT) sids[tid] = g_sorted[tile * MT + tid];
    __syncthreads();

    const uint32_t sA_u = (uint32_t)__cvta_generic_to_shared(sA);
    const uint32_t sB_u = (uint32_t)__cvta_generic_to_shared(sB4);
    const uint4* Asrc = ((MODE == 2) ? g_H1f : g_H2f) + (size_t)tile * (KTOT / 16) * 256;
    const uint4* Bt = reinterpret_cast<const uint4*>((MODE == 2) ? g_W16_2 : g_W16_3)
                      + (size_t)t * (NN * KTOT / 8);

    float acc[2][NT8][4];
#pragma unroll
    for (int i = 0; i < 2; i++)
#pragma unroll
        for (int j = 0; j < NT8; j++)
#pragma unroll
            for (int q = 0; q < 4; q++) acc[i][j][q] = 0.0f;

    auto issue = [&](int c) {
        const int s = c & 1;
        const uint4* a = Asrc + c * 1024;
#pragma unroll
        for (int q = tid; q < 1024; q += TPB)
            cp16(sA_u + ((s * 1024 + q) << 4), a + q);
        const uint4* b = Bt + (size_t)c * BCH;
#pragma unroll
        for (int q = tid; q < BCH; q += TPB)
            cp16(sB_u + ((s * BCH + q) << 4), b + q);
        CP_COMMIT();
    };

    issue(0);
    for (int c = 0; c < NCH; c++) {
        if (c + 1 < NCH) { issue(c + 1); CP_WAIT1(); }
        else             { CP_WAIT0(); }
        __syncthreads();
        const uint4* A = sA + (c & 1) * 1024;
        const uint2* B = sB2 + (c & 1) * 2 * BCH;
#pragma unroll
        for (int ksl = 0; ksl < 4; ksl++) {
            uint4 av[2];
#pragma unroll
            for (int mt = 0; mt < 2; mt++)
                av[mt] = A[(ksl * 8 + wm * 2 + mt) * 32 + lane];
#pragma unroll
            for (int nt = 0; nt < NT8; nt++) {
                const uint2 bv = B[((wn * NT8 + nt) * 4 + ksl) * 32 + lane];
#pragma unroll
                for (int mt = 0; mt < 2; mt++) MMA16(acc[mt][nt], av[mt], bv.x, bv.y);
            }
        }
        __syncthreads();
    }

    if (MODE == 3) {
        float part[2][2] = {{0.f, 0.f}, {0.f, 0.f}};
        const float* b3v = bias + t * H3;
        const float* w4v = W4 + t * H3;
#pragma unroll
        for (int nt = 0; nt < NT8; nt++) {
            const int c0 = wn * (NN / 4) + nt * 8 + 2 * tig;
            const float bb0 = __ldg(b3v + c0), bb1 = __ldg(b3v + c0 + 1);
            const float w0  = __ldg(w4v + c0), w1  = __ldg(w4v + c0 + 1);
#pragma unroll
            for (int mt = 0; mt < 2; mt++) {
                part[mt][0] += celu_f(acc[mt][nt][0] + bb0) * w0
                             + celu_f(acc[mt][nt][1] + bb1) * w1;
                part[mt][1] += celu_f(acc[mt][nt][2] + bb0) * w0
                             + celu_f(acc[mt][nt][3] + bb1) * w1;
            }
        }
#pragma unroll
        for (int mt = 0; mt < 2; mt++)
#pragma unroll
            for (int rh = 0; rh < 2; rh++) {
                part[mt][rh] += __shfl_xor_sync(0xffffffffu, part[mt][rh], 1);
                part[mt][rh] += __shfl_xor_sync(0xffffffffu, part[mt][rh], 2);
            }
        if (tig == 0) {
            const float b4v = __ldg(b4 + t);
#pragma unroll
            for (int mt = 0; mt < 2; mt++)
#pragma unroll
                for (int rh = 0; rh < 2; rh++) {
                    const int row = wm * 32 + mt * 16 + rh * 8 + g;
                    if (row < nact) {
                        const int id = sids[row];
                        const int mol = g_is64 ? batch32[2 * id] : batch32[id];
                        atomicAdd(&out[mol], part[mt][rh] + (wn == 0 ? b4v : 0.0f));
                    }
                }
        }
    } else {
        uint4* Hout = g_H2f + (size_t)tile * 12 * 256;
        const float* bv = bias + t * NN;
#pragma unroll
        for (int mt = 0; mt < 2; mt++) {
#pragma unroll
            for (int ntp = 0; ntp < NT8 / 2; ntp++) {
                const int nt = 2 * ntp;
                const int c0 = wn * (NN / 4) + nt * 8 + 2 * tig;
                const int c1 = c0 + 8;
                const float bb0 = __ldg(bv + c0), bb1 = __ldg(bv + c0 + 1);
                const float bb2 = __ldg(bv + c1), bb3 = __ldg(bv + c1 + 1);
                uint4 v;
                v.x = pack2(celu_f(acc[mt][nt][0] + bb0),     celu_f(acc[mt][nt][1] + bb1));
                v.y = pack2(celu_f(acc[mt][nt][2] + bb0),     celu_f(acc[mt][nt][3] + bb1));
                v.z = pack2(celu_f(acc[mt][nt + 1][0] + bb2), celu_f(acc[mt][nt + 1][1] + bb3));
                v.w = pack2(celu_f(acc[mt][nt + 1][2] + bb2), celu_f(acc[mt][nt + 1][3] + bb3));
                const int ks = wn * (NT8 / 2) + ntp;
                const int bm = wm * 2 + mt;
                Hout[(ks * 8 + bm) * 32 + lane] = v;
            }
        }
    }
}

// ---------------- launch ----------------
#define SM2 (32768 + 2 * H2 * 8 * 16 + 512)   // 82432
#define SM3 (32768 + 2 * H3 * 8 * 16 + 512)   // 74240

extern "C" void kernel_launch(void* const* d_in, const int* in_sizes, int n_in,
                              void* d_out, int out_size) {
    const int*   z     = (const int*)  d_in[0];
    const float* feat  = (const float*)d_in[1];
    const int*   batch = (const int*)  d_in[2];
    const float* W1 = (const float*)d_in[4];
    const float* b1 = (const float*)d_in[5];
    const float* W2 = (const float*)d_in[6];
    const float* b2 = (const float*)d_in[7];
    const float* W3 = (const float*)d_in[8];
    const float* b3 = (const float*)d_in[9];
    const float* W4 = (const float*)d_in[10];
    const float* b4 = (const float*)d_in[11];
    float* out = (float*)d_out;

    cudaFuncSetAttribute(k_gemm1,   cudaFuncAttributeMaxDynamicSharedMemorySize, G1_SM_TOTAL);
    cudaFuncSetAttribute(k_gemm<2>, cudaFuncAttributeMaxDynamicSharedMemorySize, SM2);
    cudaFuncSetAttribute(k_gemm<3>, cudaFuncAttributeMaxDynamicSharedMemorySize, SM3);

    const int initN = (out_size > PAD_MAX) ? out_size : PAD_MAX;
    k_init<<<(initN + 255) / 256, 256>>>(z, out, out_size);            // 1
    k_count<<<(N_ATOMS + 255) / 256, 256>>>(z);                        // 2
    k_scan<<<1, 1>>>();                                                // 3
    k_scatter<<<(N_ATOMS + 255) / 256, 256>>>();                       // 4
    const int prepN = 5 * H1 * KPAD / 4 + 5 * H2 * H1 / 4 + 5 * H3 * H2 / 4;
    k_prep<<<(prepN + 255) / 256, 256>>>(W1, W2, W3);                  // 5

    dim3 grid(NT_MAX, 5);
    k_gemm1<<<grid, TPB, G1_SM_TOTAL>>>(feat, b1);                     // 6 <- profiled
    k_gemm<2><<<grid, TPB, SM2>>>(batch, b2, W4, b4, out);
    k_gemm<3><<<grid, TPB, SM3>>>(batch, b3, W4, b4, out);
}

// round 8
// speedup vs baseline: 1.4878x; 1.0391x over previous
#include <cuda_runtime.h>
#include <cuda_fp16.h>
#include <math.h>
#include <stdint.h>

#define N_ATOMS 100000
#define IN_F    1008
#define KPAD    1024
#define H1      256
#define H2      192
#define H3      160
#define CALPHA  0.1f
#define MT      128
#define TPB     512
#define NT_MAX  ((N_ATOMS + MT - 1) / MT)       // 782
#define PAD_MAX ((NT_MAX + 5) * MT)

// ---------------- device scratch (static, no allocations) ----------------
__device__ int g_type[N_ATOMS];
__device__ int g_sorted[PAD_MAX];
__device__ int g_counts[5], g_poff[5], g_cursor[5], g_is64;
// fp16 fragment-order weights (KC=64): [t][kc][n8][ks4][lane] as uint2
__device__ uint2 g_W16_1[5 * H1 * KPAD / 4];
__device__ uint2 g_W16_2[5 * H2 * H1 / 4];
__device__ uint2 g_W16_3[5 * H3 * H2 / 4];
// fp16 fragment-order h1 [tile][ks(16)][bm(8)][lane(32)]
__device__ uint4 g_H1f[(size_t)(NT_MAX + 5) * 16 * 8 * 32];

// ---------------- helpers ----------------
__device__ __forceinline__ float celu_f(float x) {
    return x > 0.0f ? x : CALPHA * expm1f(x * (1.0f / CALPHA));
}
__device__ __forceinline__ uint32_t pack2(float a, float b) {
    __half2 h = __floats2half2_rn(a, b);
    return *reinterpret_cast<uint32_t*>(&h);
}
__device__ __forceinline__ void cp16(uint32_t dst, const void* src) {
    asm volatile("cp.async.cg.shared.global [%0], [%1], 16;"
                 :: "r"(dst), "l"(src) : "memory");
}
__device__ __forceinline__ void cp16z(uint32_t dst, const void* src, int valid) {
    asm volatile("cp.async.cg.shared.global [%0], [%1], 16, %2;"
                 :: "r"(dst), "l"(src), "r"(valid ? 16 : 0) : "memory");
}
#define CP_COMMIT() asm volatile("cp.async.commit_group;" ::: "memory")
#define CP_WAIT1()  asm volatile("cp.async.wait_group 1;" ::: "memory")
#define CP_WAIT0()  asm volatile("cp.async.wait_group 0;" ::: "memory")

#define MMA16(d, a, b0, b1) \
    asm volatile("mma.sync.aligned.m16n8k16.row.col.f32.f16.f16.f32 " \
                 "{%0,%1,%2,%3},{%4,%5,%6,%7},{%8,%9},{%0,%1,%2,%3};" \
                 : "+f"((d)[0]), "+f"((d)[1]), "+f"((d)[2]), "+f"((d)[3]) \
                 : "r"((a).x), "r"((a).y), "r"((a).z), "r"((a).w), \
                   "r"(b0), "r"(b1))

// ---------------- plumbing ----------------
__global__ void k_init(const int* __restrict__ z32, float* out, int n_out) {
    int i = blockIdx.x * blockDim.x + threadIdx.x;
    if (i < n_out) out[i] = 0.0f;
    if (i < PAD_MAX) g_sorted[i] = -1;
    if (i == 0) {
        g_is64 = (z32[1] == 0 && z32[3] == 0 && z32[5] == 0 && z32[7] == 0) ? 1 : 0;
        for (int t = 0; t < 5; t++) { g_counts[t] = 0; g_cursor[t] = 0; }
    }
}
__device__ __forceinline__ int z_to_type(int zv) {
    return (zv == 1) ? 0 : (zv == 6) ? 1 : (zv == 7) ? 2 : (zv == 8) ? 3 : 4;
}

// weight permute into fragment order (KC=64), fp16
template<int KC>
__device__ __forceinline__ void prep_w(uint2* dst, const float* src,
                                       int NN, int KTOT, int KIN, int i) {
    constexpr int KS = KC / 16;
    const int lane = i & 31;
    const int ks   = (i >> 5) % KS;
    int rest = i / (32 * KS);
    const int n8 = rest % (NN / 8); rest /= (NN / 8);
    const int kc = rest % (KTOT / KC);
    const int t  = rest / (KTOT / KC);
    const int n = n8 * 8 + (lane >> 2);
    const int k0 = kc * KC + ks * 16 + 2 * (lane & 3);
    const int k1 = k0 + 8;
    const float* W = src + (size_t)t * KIN * NN;
    float v00 = (k0 < KIN)     ? W[(size_t)k0 * NN + n]       : 0.0f;
    float v01 = (k0 + 1 < KIN) ? W[(size_t)(k0 + 1) * NN + n] : 0.0f;
    float v10 = (k1 < KIN)     ? W[(size_t)k1 * NN + n]       : 0.0f;
    float v11 = (k1 + 1 < KIN) ? W[(size_t)(k1 + 1) * NN + n] : 0.0f;
    dst[i] = make_uint2(pack2(v00, v01), pack2(v10, v11));
}

// fused: y=0 -> atom type count, y=1 -> weight prep
__global__ void k_count_prep(const int* __restrict__ z32,
                             const float* __restrict__ W1,
                             const float* __restrict__ W2,
                             const float* __restrict__ W3) {
    int i = blockIdx.x * blockDim.x + threadIdx.x;
    if (blockIdx.y == 0) {
        if (i >= N_ATOMS) return;
        int zv = g_is64 ? z32[2 * i] : z32[i];
        int t = z_to_type(zv);
        g_type[i] = t;
        atomicAdd(&g_counts[t], 1);
    } else {
        const int n1 = 5 * H1 * KPAD / 4, n2 = 5 * H2 * H1 / 4, n3 = 5 * H3 * H2 / 4;
        if (i < n1) prep_w<64>(g_W16_1, W1, H1, KPAD, IN_F, i);
        else if (i < n1 + n2) prep_w<64>(g_W16_2, W2, H2, H1, H1, i - n1);
        else if (i < n1 + n2 + n3) prep_w<64>(g_W16_3, W3, H3, H2, H2, i - n1 - n2);
    }
}

// scatter with inline scan (every thread computes the 5-entry padded prefix)
__global__ void k_scatter() {
    int i = blockIdx.x * blockDim.x + threadIdx.x;
    int off[5]; int acc = 0;
#pragma unroll
    for (int t = 0; t < 5; t++) {
        off[t] = acc;
        acc += ((g_counts[t] + MT - 1) / MT) * MT;
    }
    if (i == 0) {
#pragma unroll
        for (int t = 0; t < 5; t++) g_poff[t] = off[t];
    }
    if (i >= N_ATOMS) return;
    int t = g_type[i];
    int pos = off[t] + atomicAdd(&g_cursor[t], 1);
    g_sorted[pos] = i;
}

// ================= GEMM 1: fp32 features -> h1 fp16 fragments =================
// 512 threads = 16 warps as 4(M) x 4(N); warp tile 32 x 64; K-chunks of 64.
#define A_STR 68
#define G1_SM_A   0                       // 2*128*68*4 = 69632
#define G1_SM_B   69632                   // 2*2048 uint4 = 65536
#define G1_SM_IDS 135168                  // 128 ints
#define G1_SM_TOTAL 135680

__global__ void __launch_bounds__(TPB)
k_gemm1(const float* __restrict__ feat, const float* __restrict__ b1)
{
    constexpr int NCH = KPAD / 64;        // 16
    constexpr int NT8 = 8;

    const int t = blockIdx.y;
    const int cnt = g_counts[t];
    const int start = blockIdx.x * MT;
    if (start >= cnt) return;
    const int tile = (g_poff[t] >> 7) + blockIdx.x;

    extern __shared__ __align__(16) char smem[];
    float* sA  = reinterpret_cast<float*>(smem + G1_SM_A);
    uint4* sB4 = reinterpret_cast<uint4*>(smem + G1_SM_B);
    uint2* sB2 = reinterpret_cast<uint2*>(smem + G1_SM_B);
    int*   sids = reinterpret_cast<int*>(smem + G1_SM_IDS);

    const int tid = threadIdx.x;
    const int wid = tid >> 5, lane = tid & 31;
    const int wm = wid & 3, wn = wid >> 2;
    const int g = lane >> 2, tig = lane & 3;

    if (tid < MT) sids[tid] = g_sorted[tile * MT + tid];
    __syncthreads();

    const uint32_t sA_u = (uint32_t)__cvta_generic_to_shared(sA);
    const uint32_t sB_u = (uint32_t)__cvta_generic_to_shared(sB4);
    const uint4* Bt = reinterpret_cast<const uint4*>(g_W16_1) + (size_t)t * (H1 * KPAD / 8);

    float acc[2][NT8][4];
#pragma unroll
    for (int i = 0; i < 2; i++)
#pragma unroll
        for (int j = 0; j < NT8; j++)
#pragma unroll
            for (int q = 0; q < 4; q++) acc[i][j][q] = 0.0f;

    auto issue = [&](int c) {
        const int s = c & 1;
        // A: 128 rows x 64 fp32 (2048 float4)
#pragma unroll
        for (int q = tid; q < MT * 16; q += TPB) {
            const int r = q >> 4, fq = q & 15;
            const int id = sids[r];
            const int k = c * 64 + fq * 4;
            const int v = (id >= 0) && (k < IN_F);
            const float* src = feat + (v ? ((size_t)id * IN_F + k) : 0);
            cp16z(sA_u + (((s * MT + r) * A_STR + fq * 4) << 2), src, v);
        }
        // B: 2048 uint4 (fragment order)
        const uint4* b = Bt + (size_t)c * 2048;
#pragma unroll
        for (int q = tid; q < 2048; q += TPB)
            cp16(sB_u + ((s * 2048 + q) << 4), b + q);
        CP_COMMIT();
    };

    issue(0);
    for (int c = 0; c < NCH; c++) {
        if (c + 1 < NCH) { issue(c + 1); CP_WAIT1(); }
        else             { CP_WAIT0(); }
        __syncthreads();
        const float* A = sA + (c & 1) * MT * A_STR;
        const uint2* B = sB2 + (c & 1) * 4096;
#pragma unroll
        for (int ksl = 0; ksl < 4; ksl++) {
            const int k0 = ksl * 16 + 2 * tig;
            uint4 av[2];
#pragma unroll
            for (int mt = 0; mt < 2; mt++) {
                const int r0 = wm * 32 + mt * 16 + g;
                float2 p0 = *reinterpret_cast<const float2*>(A + r0 * A_STR + k0);
                float2 p1 = *reinterpret_cast<const float2*>(A + (r0 + 8) * A_STR + k0);
                float2 p2 = *reinterpret_cast<const float2*>(A + r0 * A_STR + k0 + 8);
                float2 p3 = *reinterpret_cast<const float2*>(A + (r0 + 8) * A_STR + k0 + 8);
                av[mt].x = pack2(p0.x, p0.y);
                av[mt].y = pack2(p1.x, p1.y);
                av[mt].z = pack2(p2.x, p2.y);
                av[mt].w = pack2(p3.x, p3.y);
            }
#pragma unroll
            for (int nt = 0; nt < NT8; nt++) {
                const uint2 bv = B[((wn * NT8 + nt) * 4 + ksl) * 32 + lane];
#pragma unroll
                for (int mt = 0; mt < 2; mt++) MMA16(acc[mt][nt], av[mt], bv.x, bv.y);
            }
        }
        __syncthreads();
    }

    // epilogue: bias+celu -> h1 fragments [ks16][bm8][lane32]
    uint4* Hout = g_H1f + (size_t)tile * 16 * 256;
    const float* bv = b1 + t * H1;
#pragma unroll
    for (int mt = 0; mt < 2; mt++) {
#pragma unroll
        for (int ntp = 0; ntp < NT8 / 2; ntp++) {
            const int nt = 2 * ntp;
            const int c0 = wn * 64 + nt * 8 + 2 * tig;
            const int c1 = c0 + 8;
            const float bb0 = __ldg(bv + c0), bb1 = __ldg(bv + c0 + 1);
            const float bb2 = __ldg(bv + c1), bb3 = __ldg(bv + c1 + 1);
            uint4 v;
            v.x = pack2(celu_f(acc[mt][nt][0] + bb0),     celu_f(acc[mt][nt][1] + bb1));
            v.y = pack2(celu_f(acc[mt][nt][2] + bb0),     celu_f(acc[mt][nt][3] + bb1));
            v.z = pack2(celu_f(acc[mt][nt + 1][0] + bb2), celu_f(acc[mt][nt + 1][1] + bb3));
            v.w = pack2(celu_f(acc[mt][nt + 1][2] + bb2), celu_f(acc[mt][nt + 1][3] + bb3));
            const int ks = wn * 4 + ntp;
            const int bm = wm * 2 + mt;
            Hout[(ks * 8 + bm) * 32 + lane] = v;
        }
    }
}

// ================= GEMM 2+3 fused: h1 -> h2 (smem) -> out =================
// 512 threads = 16 warps as 4(M) x 4(N); K-chunks of 64; h2 fragments in SMEM.
#define G2_SM_A   0                        // 2*1024 uint4 = 32768
#define G2_SM_B   32768                    // 2*1536 uint4 = 49152
#define G2_SM_H2  81920                    // 3072 uint4 = 49152
#define G2_SM_IDS 131072                   // 128 ints
#define G2_SM_TOTAL 131584

__global__ void __launch_bounds__(TPB)
k_gemm23(const int* __restrict__ batch32,
         const float* __restrict__ b2, const float* __restrict__ b3,
         const float* __restrict__ W4, const float* __restrict__ b4,
         float* __restrict__ out)
{
    const int t = blockIdx.y;
    const int cnt = g_counts[t];
    const int start = blockIdx.x * MT;
    if (start >= cnt) return;
    const int nact = min(MT, cnt - start);
    const int tile = (g_poff[t] >> 7) + blockIdx.x;

    extern __shared__ __align__(16) char smem[];
    uint4* sA   = reinterpret_cast<uint4*>(smem + G2_SM_A);
    uint4* sB4  = reinterpret_cast<uint4*>(smem + G2_SM_B);
    uint2* sB2  = reinterpret_cast<uint2*>(smem + G2_SM_B);
    uint4* sH2  = reinterpret_cast<uint4*>(smem + G2_SM_H2);
    int*   sids = reinterpret_cast<int*>(smem + G2_SM_IDS);

    const int tid = threadIdx.x;
    const int wid = tid >> 5, lane = tid & 31;
    const int wm = wid & 3, wn = wid >> 2;
    const int g = lane >> 2, tig = lane & 3;

    if (tid < MT) sids[tid] = g_sorted[tile * MT + tid];
    __syncthreads();

    const uint32_t sA_u = (uint32_t)__cvta_generic_to_shared(sA);
    const uint32_t sB_u = (uint32_t)__cvta_generic_to_shared(sB4);

    // ---------- Layer 2: A = g_H1f, B = g_W16_2, NN=192, K=256 ----------
    {
        constexpr int NCH = 4, NT8 = 6, BCH = H2 * 8;   // 1536 uint4
        const uint4* Asrc = g_H1f + (size_t)tile * 16 * 256;
        const uint4* Bt = reinterpret_cast<const uint4*>(g_W16_2) + (size_t)t * (H2 * H1 / 8);

        float acc[2][NT8][4];
#pragma unroll
        for (int i = 0; i < 2; i++)
#pragma unroll
            for (int j = 0; j < NT8; j++)
#pragma unroll
                for (int q = 0; q < 4; q++) acc[i][j][q] = 0.0f;

        auto issue = [&](int c) {
            const int s = c & 1;
            const uint4* a = Asrc + c * 1024;
#pragma unroll
            for (int q = tid; q < 1024; q += TPB)
                cp16(sA_u + ((s * 1024 + q) << 4), a + q);
            const uint4* b = Bt + (size_t)c * BCH;
#pragma unroll
            for (int q = tid; q < BCH; q += TPB)
                cp16(sB_u + ((s * BCH + q) << 4), b + q);
            CP_COMMIT();
        };

        issue(0);
        for (int c = 0; c < NCH; c++) {
            if (c + 1 < NCH) { issue(c + 1); CP_WAIT1(); }
            else             { CP_WAIT0(); }
            __syncthreads();
            const uint4* A = sA + (c & 1) * 1024;
            const uint2* B = sB2 + (c & 1) * 2 * BCH;
#pragma unroll
            for (int ksl = 0; ksl < 4; ksl++) {
                uint4 av[2];
#pragma unroll
                for (int mt = 0; mt < 2; mt++)
                    av[mt] = A[(ksl * 8 + wm * 2 + mt) * 32 + lane];
#pragma unroll
                for (int nt = 0; nt < NT8; nt++) {
                    const uint2 bv = B[((wn * NT8 + nt) * 4 + ksl) * 32 + lane];
#pragma unroll
                    for (int mt = 0; mt < 2; mt++) MMA16(acc[mt][nt], av[mt], bv.x, bv.y);
                }
            }
            __syncthreads();
        }

        // epilogue 2 -> h2 fragments in SMEM [ks12][bm8][lane32]
        const float* bv = b2 + t * H2;
#pragma unroll
        for (int mt = 0; mt < 2; mt++) {
#pragma unroll
            for (int ntp = 0; ntp < NT8 / 2; ntp++) {
                const int nt = 2 * ntp;
                const int c0 = wn * (H2 / 4) + nt * 8 + 2 * tig;
                const int c1 = c0 + 8;
                const float bb0 = __ldg(bv + c0), bb1 = __ldg(bv + c0 + 1);
                const float bb2 = __ldg(bv + c1), bb3 = __ldg(bv + c1 + 1);
                uint4 v;
                v.x = pack2(celu_f(acc[mt][nt][0] + bb0),     celu_f(acc[mt][nt][1] + bb1));
                v.y = pack2(celu_f(acc[mt][nt][2] + bb0),     celu_f(acc[mt][nt][3] + bb1));
                v.z = pack2(celu_f(acc[mt][nt + 1][0] + bb2), celu_f(acc[mt][nt + 1][1] + bb3));
                v.w = pack2(celu_f(acc[mt][nt + 1][2] + bb2), celu_f(acc[mt][nt + 1][3] + bb3));
                const int ks = wn * (NT8 / 2) + ntp;
                const int bm = wm * 2 + mt;
                sH2[(ks * 8 + bm) * 32 + lane] = v;
            }
        }
    }
    __syncthreads();

    // ---------- Layer 3 + 4: A = sH2, B = g_W16_3, NN=160, K=192 ----------
    {
        constexpr int NCH = 3, NT8 = 5, BCH = H3 * 8;   // 1280 uint4
        const uint4* Bt = reinterpret_cast<const uint4*>(g_W16_3) + (size_t)t * (H3 * H2 / 8);

        float acc[2][NT8][4];
#pragma unroll
        for (int i = 0; i < 2; i++)
#pragma unroll
            for (int j = 0; j < NT8; j++)
#pragma unroll
                for (int q = 0; q < 4; q++) acc[i][j][q] = 0.0f;

        auto issueB = [&](int c) {
            const uint4* b = Bt + (size_t)c * BCH;
#pragma unroll
            for (int q = tid; q < BCH; q += TPB)
                cp16(sB_u + (((c & 1) * BCH + q) << 4), b + q);
            CP_COMMIT();
        };

        issueB(0);
        for (int c = 0; c < NCH; c++) {
            if (c + 1 < NCH) { issueB(c + 1); CP_WAIT1(); }
            else             { CP_WAIT0(); }
            __syncthreads();
            const uint2* B = sB2 + (c & 1) * 2 * BCH;
#pragma unroll
            for (int ksl = 0; ksl < 4; ksl++) {
                uint4 av[2];
#pragma unroll
                for (int mt = 0; mt < 2; mt++)
                    av[mt] = sH2[((c * 4 + ksl) * 8 + wm * 2 + mt) * 32 + lane];
#pragma unroll
                for (int nt = 0; nt < NT8; nt++) {
                    const uint2 bv = B[((wn * NT8 + nt) * 4 + ksl) * 32 + lane];
#pragma unroll
                    for (int mt = 0; mt < 2; mt++) MMA16(acc[mt][nt], av[mt], bv.x, bv.y);
                }
            }
            __syncthreads();
        }

        // epilogue 3 + layer 4
        float part[2][2] = {{0.f, 0.f}, {0.f, 0.f}};
        const float* b3v = b3 + t * H3;
        const float* w4v = W4 + t * H3;
#pragma unroll
        for (int nt = 0; nt < NT8; nt++) {
            const int c0 = wn * (H3 / 4) + nt * 8 + 2 * tig;
            const float bb0 = __ldg(b3v + c0), bb1 = __ldg(b3v + c0 + 1);
            const float w0  = __ldg(w4v + c0), w1  = __ldg(w4v + c0 + 1);
#pragma unroll
            for (int mt = 0; mt < 2; mt++) {
                part[mt][0] += celu_f(acc[mt][nt][0] + bb0) * w0
                             + celu_f(acc[mt][nt][1] + bb1) * w1;
                part[mt][1] += celu_f(acc[mt][nt][2] + bb0) * w0
                             + celu_f(acc[mt][nt][3] + bb1) * w1;
            }
        }
#pragma unroll
        for (int mt = 0; mt < 2; mt++)
#pragma unroll
            for (int rh = 0; rh < 2; rh++) {
                part[mt][rh] += __shfl_xor_sync(0xffffffffu, part[mt][rh], 1);
                part[mt][rh] += __shfl_xor_sync(0xffffffffu, part[mt][rh], 2);
            }
        if (tig == 0) {
            const float b4v = __ldg(b4 + t);
#pragma unroll
            for (int mt = 0; mt < 2; mt++)
#pragma unroll
                for (int rh = 0; rh < 2; rh++) {
                    const int row = wm * 32 + mt * 16 + rh * 8 + g;
                    if (row < nact) {
                        const int id = sids[row];
                        const int mol = g_is64 ? batch32[2 * id] : batch32[id];
                        atomicAdd(&out[mol], part[mt][rh] + (wn == 0 ? b4v : 0.0f));
                    }
                }
        }
    }
}

// ---------------- launch ----------------
extern "C" void kernel_launch(void* const* d_in, const int* in_sizes, int n_in,
                              void* d_out, int out_size) {
    const int*   z     = (const int*)  d_in[0];
    const float* feat  = (const float*)d_in[1];
    const int*   batch = (const int*)  d_in[2];
    const float* W1 = (const float*)d_in[4];
    const float* b1 = (const float*)d_in[5];
    const float* W2 = (const float*)d_in[6];
    const float* b2 = (const float*)d_in[7];
    const float* W3 = (const float*)d_in[8];
    const float* b3 = (const float*)d_in[9];
    const float* W4 = (const float*)d_in[10];
    const float* b4 = (const float*)d_in[11];
    float* out = (float*)d_out;

    cudaFuncSetAttribute(k_gemm1,  cudaFuncAttributeMaxDynamicSharedMemorySize, G1_SM_TOTAL);
    cudaFuncSetAttribute(k_gemm23, cudaFuncAttributeMaxDynamicSharedMemorySize, G2_SM_TOTAL);

    const int initN = (out_size > PAD_MAX) ? out_size : PAD_MAX;
    const int prepN = 5 * H1 * KPAD / 4 + 5 * H2 * H1 / 4 + 5 * H3 * H2 / 4;
    const int cpN = (prepN > N_ATOMS) ? prepN : N_ATOMS;

    k_init<<<(initN + 255) / 256, 256>>>(z, out, out_size);            // 1
    dim3 cpg((cpN + 255) / 256, 2);
    k_count_prep<<<cpg, 256>>>(z, W1, W2, W3);                         // 2
    k_scatter<<<(N_ATOMS + 255) / 256, 256>>>();                       // 3

    dim3 grid(NT_MAX, 5);
    k_gemm1<<<grid, TPB, G1_SM_TOTAL>>>(feat, b1);                     // 4 <- profiled
    k_gemm23<<<grid, TPB, G2_SM_TOTAL>>>(batch, b2, b3, W4, b4, out);  // 5
}

// round 9
// speedup vs baseline: 1.5870x; 1.0667x over previous
#include <cuda_runtime.h>
#include <cuda_fp16.h>
#include <math.h>
#include <stdint.h>

#define N_ATOMS 100000
#define IN_F    1008
#define KPAD    1024
#define H1      256
#define H2      192
#define H3      160
#define CALPHA  0.1f
#define MT      128
#define TPB     512
#define NT_MAX  ((N_ATOMS + MT - 1) / MT)       // 782
#define PAD_MAX ((NT_MAX + 5) * MT)

// ---------------- device scratch (static, no allocations) ----------------
__device__ int g_type[N_ATOMS];
__device__ int g_sorted[PAD_MAX];
__device__ int g_counts[5], g_poff[5], g_cursor[5], g_is64;
// fp16 weights, uint4-fragment order: [t][kc][n8][kp(2)][lane] uint4
//   uint4.xy = ks=2kp fragment (b0,b1), uint4.zw = ks=2kp+1 (b0,b1)
__device__ uint2 g_W16_1[5 * H1 * KPAD / 4];
__device__ uint2 g_W16_2[5 * H2 * H1 / 4];
__device__ uint2 g_W16_3[5 * H3 * H2 / 4];
// fp16 fragment-order h1 [tile][ks(16)][bm(8)][lane(32)]
__device__ uint4 g_H1f[(size_t)(NT_MAX + 5) * 16 * 8 * 32];

// ---------------- helpers ----------------
__device__ __forceinline__ float celu_f(float x) {
    return x > 0.0f ? x : CALPHA * expm1f(x * (1.0f / CALPHA));
}
__device__ __forceinline__ uint32_t pack2(float a, float b) {
    __half2 h = __floats2half2_rn(a, b);
    return *reinterpret_cast<uint32_t*>(&h);
}
__device__ __forceinline__ void cp16(uint32_t dst, const void* src) {
    asm volatile("cp.async.cg.shared.global [%0], [%1], 16;"
                 :: "r"(dst), "l"(src) : "memory");
}
__device__ __forceinline__ void cp16z(uint32_t dst, const void* src, int valid) {
    asm volatile("cp.async.cg.shared.global [%0], [%1], 16, %2;"
                 :: "r"(dst), "l"(src), "r"(valid ? 16 : 0) : "memory");
}
#define CP_COMMIT() asm volatile("cp.async.commit_group;" ::: "memory")
#define CP_WAIT1()  asm volatile("cp.async.wait_group 1;" ::: "memory")
#define CP_WAIT0()  asm volatile("cp.async.wait_group 0;" ::: "memory")

#define MMA16(d, a, b0, b1) \
    asm volatile("mma.sync.aligned.m16n8k16.row.col.f32.f16.f16.f32 " \
                 "{%0,%1,%2,%3},{%4,%5,%6,%7},{%8,%9},{%0,%1,%2,%3};" \
                 : "+f"((d)[0]), "+f"((d)[1]), "+f"((d)[2]), "+f"((d)[3]) \
                 : "r"((a).x), "r"((a).y), "r"((a).z), "r"((a).w), \
                   "r"(b0), "r"(b1))

// ---------------- plumbing ----------------
__global__ void k_init(const int* __restrict__ z32, float* out, int n_out) {
    int i = blockIdx.x * blockDim.x + threadIdx.x;
    if (i < n_out) out[i] = 0.0f;
    if (i < PAD_MAX) g_sorted[i] = -1;
    if (i == 0) {
        g_is64 = (z32[1] == 0 && z32[3] == 0 && z32[5] == 0 && z32[7] == 0) ? 1 : 0;
        for (int t = 0; t < 5; t++) { g_counts[t] = 0; g_cursor[t] = 0; }
    }
}
__device__ __forceinline__ int z_to_type(int zv) {
    return (zv == 1) ? 0 : (zv == 6) ? 1 : (zv == 7) ? 2 : (zv == 8) ? 3 : 4;
}

// weight permute into uint4-fragment order (KC=64), fp16
template<int KC>
__device__ __forceinline__ void prep_w(uint2* dst, const float* src,
                                       int NN, int KTOT, int KIN, int i) {
    constexpr int KS = KC / 16;
    const int lane = i & 31;
    const int ks   = (i >> 5) % KS;
    int rest = i / (32 * KS);
    const int n8 = rest % (NN / 8); rest /= (NN / 8);
    const int kc = rest % (KTOT / KC);
    const int t  = rest / (KTOT / KC);
    const int n = n8 * 8 + (lane >> 2);
    const int k0 = kc * KC + ks * 16 + 2 * (lane & 3);
    const int k1 = k0 + 8;
    const float* W = src + (size_t)t * KIN * NN;
    float v00 = (k0 < KIN)     ? W[(size_t)k0 * NN + n]       : 0.0f;
    float v01 = (k0 + 1 < KIN) ? W[(size_t)(k0 + 1) * NN + n] : 0.0f;
    float v10 = (k1 < KIN)     ? W[(size_t)k1 * NN + n]       : 0.0f;
    float v11 = (k1 + 1 < KIN) ? W[(size_t)(k1 + 1) * NN + n] : 0.0f;
    // uint4-pair layout: group = (t,kc,n8); inside: (ks>>1)*64 + lane*2 + (ks&1)
    const int group = (t * (KTOT / KC) + kc) * (NN / 8) + n8;
    dst[(size_t)group * (KS * 32) + (ks >> 1) * 64 + lane * 2 + (ks & 1)] =
        make_uint2(pack2(v00, v01), pack2(v10, v11));
}

// fused: y=0 -> atom type count, y=1 -> weight prep
__global__ void k_count_prep(const int* __restrict__ z32,
                             const float* __restrict__ W1,
                             const float* __restrict__ W2,
                             const float* __restrict__ W3) {
    int i = blockIdx.x * blockDim.x + threadIdx.x;
    if (blockIdx.y == 0) {
        if (i >= N_ATOMS) return;
        int zv = g_is64 ? z32[2 * i] : z32[i];
        int t = z_to_type(zv);
        g_type[i] = t;
        atomicAdd(&g_counts[t], 1);
    } else {
        const int n1 = 5 * H1 * KPAD / 4, n2 = 5 * H2 * H1 / 4, n3 = 5 * H3 * H2 / 4;
        if (i < n1) prep_w<64>(g_W16_1, W1, H1, KPAD, IN_F, i);
        else if (i < n1 + n2) prep_w<64>(g_W16_2, W2, H2, H1, H1, i - n1);
        else if (i < n1 + n2 + n3) prep_w<64>(g_W16_3, W3, H3, H2, H2, i - n1 - n2);
    }
}

// scatter with inline scan
__global__ void k_scatter() {
    int i = blockIdx.x * blockDim.x + threadIdx.x;
    int off[5]; int acc = 0;
#pragma unroll
    for (int t = 0; t < 5; t++) {
        off[t] = acc;
        acc += ((g_counts[t] + MT - 1) / MT) * MT;
    }
    if (i == 0) {
#pragma unroll
        for (int t = 0; t < 5; t++) g_poff[t] = off[t];
    }
    if (i >= N_ATOMS) return;
    int t = g_type[i];
    int pos = off[t] + atomicAdd(&g_cursor[t], 1);
    g_sorted[pos] = i;
}

// ================= GEMM 1: fp32 features (swizzled smem) -> h1 fp16 fragments =================
// 512 threads = 16 warps as 4(M) x 4(N); warp tile 32 x 64; K-chunks of 64.
// A staging: 128 rows x 64 fp32, row stride 64, XOR swizzle:
//   float4 store index j -> j ^ ((row&7)<<1); float2 read index p -> p ^ ((row&7)<<2)
#define G1_SM_A   0                       // 2*128*64*4 = 65536
#define G1_SM_B   65536                   // 2*2048 uint4 = 65536
#define G1_SM_IDS 131072                  // 128 ints
#define G1_SM_TOTAL 131584

__global__ void __launch_bounds__(TPB)
k_gemm1(const float* __restrict__ feat, const float* __restrict__ b1)
{
    constexpr int NCH = KPAD / 64;        // 16
    constexpr int NT8 = 8;

    const int t = blockIdx.y;
    const int cnt = g_counts[t];
    const int start = blockIdx.x * MT;
    if (start >= cnt) return;
    const int tile = (g_poff[t] >> 7) + blockIdx.x;

    extern __shared__ __align__(16) char smem[];
    float* sA  = reinterpret_cast<float*>(smem + G1_SM_A);
    uint4* sB4 = reinterpret_cast<uint4*>(smem + G1_SM_B);
    int*   sids = reinterpret_cast<int*>(smem + G1_SM_IDS);

    const int tid = threadIdx.x;
    const int wid = tid >> 5, lane = tid & 31;
    const int wm = wid & 3, wn = wid >> 2;
    const int g = lane >> 2, tig = lane & 3;

    if (tid < MT) sids[tid] = g_sorted[tile * MT + tid];
    __syncthreads();

    const uint32_t sA_u = (uint32_t)__cvta_generic_to_shared(sA);
    const uint32_t sB_u = (uint32_t)__cvta_generic_to_shared(sB4);
    const uint4* Bt = reinterpret_cast<const uint4*>(g_W16_1) + (size_t)t * (H1 * KPAD / 8);

    float acc[2][NT8][4];
#pragma unroll
    for (int i = 0; i < 2; i++)
#pragma unroll
        for (int j = 0; j < NT8; j++)
#pragma unroll
            for (int q = 0; q < 4; q++) acc[i][j][q] = 0.0f;

    auto issue = [&](int c) {
        const int s = c & 1;
        // A: 128 rows x 64 fp32, swizzled float4 stores
#pragma unroll
        for (int q = tid; q < MT * 16; q += TPB) {
            const int r = q >> 4, fq = q & 15;
            const int id = sids[r];
            const int k = c * 64 + fq * 4;
            const int v = (id >= 0) && (k < IN_F);
            const float* src = feat + (v ? ((size_t)id * IN_F + k) : 0);
            const int jsw = fq ^ ((r & 7) << 1);
            cp16z(sA_u + ((((s * MT + r) << 6) + (jsw << 2)) << 2), src, v);
        }
        // B: 2048 uint4 (fragment order, contiguous)
        const uint4* b = Bt + (size_t)c * 2048;
#pragma unroll
        for (int q = tid; q < 2048; q += TPB)
            cp16(sB_u + ((s * 2048 + q) << 4), b + q);
        CP_COMMIT();
    };

    issue(0);
    for (int c = 0; c < NCH; c++) {
        if (c + 1 < NCH) { issue(c + 1); CP_WAIT1(); }
        else             { CP_WAIT0(); }
        __syncthreads();
        const float* A = sA + (c & 1) * MT * 64;
        const uint4* B = sB4 + (c & 1) * 2048;
        const int sw = g << 2;
#pragma unroll
        for (int kp = 0; kp < 2; kp++) {
            uint4 av0[2], av1[2];
#pragma unroll
            for (int mt = 0; mt < 2; mt++) {
                const int r0 = (wm * 32 + mt * 16 + g) << 6;
                const int r1 = r0 + (8 << 6);
                // ksl = 2*kp
                {
                    const int p0 = ((16 * kp + tig) ^ sw) << 1;
                    const int p1 = ((16 * kp + tig + 4) ^ sw) << 1;
                    float2 f00 = *reinterpret_cast<const float2*>(A + r0 + p0);
                    float2 f10 = *reinterpret_cast<const float2*>(A + r1 + p0);
                    float2 f01 = *reinterpret_cast<const float2*>(A + r0 + p1);
                    float2 f11 = *reinterpret_cast<const float2*>(A + r1 + p1);
                    av0[mt].x = pack2(f00.x, f00.y);
                    av0[mt].y = pack2(f10.x, f10.y);
                    av0[mt].z = pack2(f01.x, f01.y);
                    av0[mt].w = pack2(f11.x, f11.y);
                }
                // ksl = 2*kp+1
                {
                    const int p0 = ((16 * kp + 8 + tig) ^ sw) << 1;
                    const int p1 = ((16 * kp + 8 + tig + 4) ^ sw) << 1;
                    float2 f00 = *reinterpret_cast<const float2*>(A + r0 + p0);
                    float2 f10 = *reinterpret_cast<const float2*>(A + r1 + p0);
                    float2 f01 = *reinterpret_cast<const float2*>(A + r0 + p1);
                    float2 f11 = *reinterpret_cast<const float2*>(A + r1 + p1);
                    av1[mt].x = pack2(f00.x, f00.y);
                    av1[mt].y = pack2(f10.x, f10.y);
                    av1[mt].z = pack2(f01.x, f01.y);
                    av1[mt].w = pack2(f11.x, f11.y);
                }
            }
#pragma unroll
            for (int nt = 0; nt < NT8; nt++) {
                const uint4 bq = B[((wn * NT8 + nt) << 6) + (kp << 5) + lane];
#pragma unroll
                for (int mt = 0; mt < 2; mt++) {
                    MMA16(acc[mt][nt], av0[mt], bq.x, bq.y);
                    MMA16(acc[mt][nt], av1[mt], bq.z, bq.w);
                }
            }
        }
        __syncthreads();
    }

    // epilogue: bias+celu -> h1 fragments [ks16][bm8][lane32]
    uint4* Hout = g_H1f + (size_t)tile * 16 * 256;
    const float* bv = b1 + t * H1;
#pragma unroll
    for (int mt = 0; mt < 2; mt++) {
#pragma unroll
        for (int ntp = 0; ntp < NT8 / 2; ntp++) {
            const int nt = 2 * ntp;
            const int c0 = wn * 64 + nt * 8 + 2 * tig;
            const int c1 = c0 + 8;
            const float bb0 = __ldg(bv + c0), bb1 = __ldg(bv + c0 + 1);
            const float bb2 = __ldg(bv + c1), bb3 = __ldg(bv + c1 + 1);
            uint4 v;
            v.x = pack2(celu_f(acc[mt][nt][0] + bb0),     celu_f(acc[mt][nt][1] + bb1));
            v.y = pack2(celu_f(acc[mt][nt][2] + bb0),     celu_f(acc[mt][nt][3] + bb1));
            v.z = pack2(celu_f(acc[mt][nt + 1][0] + bb2), celu_f(acc[mt][nt + 1][1] + bb3));
            v.w = pack2(celu_f(acc[mt][nt + 1][2] + bb2), celu_f(acc[mt][nt + 1][3] + bb3));
            const int ks = wn * 4 + ntp;
            const int bm = wm * 2 + mt;
            Hout[(ks * 8 + bm) * 32 + lane] = v;
        }
    }
}

// ================= GEMM 2+3 fused: h1 -> h2 (smem) -> out =================
#define G2_SM_A   0                        // 2*1024 uint4 = 32768
#define G2_SM_B   32768                    // 2*1536 uint4 = 49152
#define G2_SM_H2  81920                    // 3072 uint4 = 49152
#define G2_SM_IDS 131072                   // 128 ints
#define G2_SM_TOTAL 131584

__global__ void __launch_bounds__(TPB)
k_gemm23(const int* __restrict__ batch32,
         const float* __restrict__ b2, const float* __restrict__ b3,
         const float* __restrict__ W4, const float* __restrict__ b4,
         float* __restrict__ out)
{
    const int t = blockIdx.y;
    const int cnt = g_counts[t];
    const int start = blockIdx.x * MT;
    if (start >= cnt) return;
    const int nact = min(MT, cnt - start);
    const int tile = (g_poff[t] >> 7) + blockIdx.x;

    extern __shared__ __align__(16) char smem[];
    uint4* sA   = reinterpret_cast<uint4*>(smem + G2_SM_A);
    uint4* sB4  = reinterpret_cast<uint4*>(smem + G2_SM_B);
    uint4* sH2  = reinterpret_cast<uint4*>(smem + G2_SM_H2);
    int*   sids = reinterpret_cast<int*>(smem + G2_SM_IDS);

    const int tid = threadIdx.x;
    const int wid = tid >> 5, lane = tid & 31;
    const int wm = wid & 3, wn = wid >> 2;
    const int g = lane >> 2, tig = lane & 3;

    if (tid < MT) sids[tid] = g_sorted[tile * MT + tid];
    __syncthreads();

    const uint32_t sA_u = (uint32_t)__cvta_generic_to_shared(sA);
    const uint32_t sB_u = (uint32_t)__cvta_generic_to_shared(sB4);

    // ---------- Layer 2: A = g_H1f, B = g_W16_2, NN=192, K=256 ----------
    {
        constexpr int NCH = 4, NT8 = 6, BCH = H2 * 8;   // 1536 uint4
        const uint4* Asrc = g_H1f + (size_t)tile * 16 * 256;
        const uint4* Bt = reinterpret_cast<const uint4*>(g_W16_2) + (size_t)t * (H2 * H1 / 8);

        float acc[2][NT8][4];
#pragma unroll
        for (int i = 0; i < 2; i++)
#pragma unroll
            for (int j = 0; j < NT8; j++)
#pragma unroll
                for (int q = 0; q < 4; q++) acc[i][j][q] = 0.0f;

        auto issue = [&](int c) {
            const int s = c & 1;
            const uint4* a = Asrc + c * 1024;
#pragma unroll
            for (int q = tid; q < 1024; q += TPB)
                cp16(sA_u + ((s * 1024 + q) << 4), a + q);
            const uint4* b = Bt + (size_t)c * BCH;
#pragma unroll
            for (int q = tid; q < BCH; q += TPB)
                cp16(sB_u + ((s * BCH + q) << 4), b + q);
            CP_COMMIT();
        };

        issue(0);
        for (int c = 0; c < NCH; c++) {
            if (c + 1 < NCH) { issue(c + 1); CP_WAIT1(); }
            else             { CP_WAIT0(); }
            __syncthreads();
            const uint4* A = sA + (c & 1) * 1024;
            const uint4* B = sB4 + (c & 1) * BCH;
#pragma unroll
            for (int kp = 0; kp < 2; kp++) {
                uint4 av0[2], av1[2];
#pragma unroll
                for (int mt = 0; mt < 2; mt++) {
                    av0[mt] = A[((2 * kp) * 8 + wm * 2 + mt) * 32 + lane];
                    av1[mt] = A[((2 * kp + 1) * 8 + wm * 2 + mt) * 32 + lane];
                }
#pragma unroll
                for (int nt = 0; nt < NT8; nt++) {
                    const uint4 bq = B[((wn * NT8 + nt) << 6) + (kp << 5) + lane];
#pragma unroll
                    for (int mt = 0; mt < 2; mt++) {
                        MMA16(acc[mt][nt], av0[mt], bq.x, bq.y);
                        MMA16(acc[mt][nt], av1[mt], bq.z, bq.w);
                    }
                }
            }
            __syncthreads();
        }

        // epilogue 2 -> h2 fragments in SMEM [ks12][bm8][lane32]
        const float* bv = b2 + t * H2;
#pragma unroll
        for (int mt = 0; mt < 2; mt++) {
#pragma unroll
            for (int ntp = 0; ntp < NT8 / 2; ntp++) {
                const int nt = 2 * ntp;
                const int c0 = wn * (H2 / 4) + nt * 8 + 2 * tig;
                const int c1 = c0 + 8;
                const float bb0 = __ldg(bv + c0), bb1 = __ldg(bv + c0 + 1);
                const float bb2 = __ldg(bv + c1), bb3 = __ldg(bv + c1 + 1);
                uint4 v;
                v.x = pack2(celu_f(acc[mt][nt][0] + bb0),     celu_f(acc[mt][nt][1] + bb1));
                v.y = pack2(celu_f(acc[mt][nt][2] + bb0),     celu_f(acc[mt][nt][3] + bb1));
                v.z = pack2(celu_f(acc[mt][nt + 1][0] + bb2), celu_f(acc[mt][nt + 1][1] + bb3));
                v.w = pack2(celu_f(acc[mt][nt + 1][2] + bb2), celu_f(acc[mt][nt + 1][3] + bb3));
                const int ks = wn * (NT8 / 2) + ntp;
                const int bm = wm * 2 + mt;
                sH2[(ks * 8 + bm) * 32 + lane] = v;
            }
        }
    }
    __syncthreads();

    // ---------- Layer 3 + 4: A = sH2, B = g_W16_3, NN=160, K=192 ----------
    {
        constexpr int NCH = 3, NT8 = 5, BCH = H3 * 8;   // 1280 uint4
        const uint4* Bt = reinterpret_cast<const uint4*>(g_W16_3) + (size_t)t * (H3 * H2 / 8);

        float acc[2][NT8][4];
#pragma unroll
        for (int i = 0; i < 2; i++)
#pragma unroll
            for (int j = 0; j < NT8; j++)
#pragma unroll
                for (int q = 0; q < 4; q++) acc[i][j][q] = 0.0f;

        auto issueB = [&](int c) {
            const uint4* b = Bt + (size_t)c * BCH;
#pragma unroll
            for (int q = tid; q < BCH; q += TPB)
                cp16(sB_u + (((c & 1) * BCH + q) << 4), b + q);
            CP_COMMIT();
        };

        issueB(0);
        for (int c = 0; c < NCH; c++) {
            if (c + 1 < NCH) { issueB(c + 1); CP_WAIT1(); }
            else             { CP_WAIT0(); }
            __syncthreads();
            const uint4* B = sB4 + (c & 1) * BCH;
#pragma unroll
            for (int kp = 0; kp < 2; kp++) {
                uint4 av0[2], av1[2];
#pragma unroll
                for (int mt = 0; mt < 2; mt++) {
                    av0[mt] = sH2[((c * 4 + 2 * kp) * 8 + wm * 2 + mt) * 32 + lane];
                    av1[mt] = sH2[((c * 4 + 2 * kp + 1) * 8 + wm * 2 + mt) * 32 + lane];
                }
#pragma unroll
                for (int nt = 0; nt < NT8; nt++) {
                    const uint4 bq = B[((wn * NT8 + nt) << 6) + (kp << 5) + lane];
#pragma unroll
                    for (int mt = 0; mt < 2; mt++) {
                        MMA16(acc[mt][nt], av0[mt], bq.x, bq.y);
                        MMA16(acc[mt][nt], av1[mt], bq.z, bq.w);
                    }
                }
            }
            __syncthreads();
        }

        // epilogue 3 + layer 4
        float part[2][2] = {{0.f, 0.f}, {0.f, 0.f}};
        const float* b3v = b3 + t * H3;
        const float* w4v = W4 + t * H3;
#pragma unroll
        for (int nt = 0; nt < NT8; nt++) {
            const int c0 = wn * (H3 / 4) + nt * 8 + 2 * tig;
            const float bb0 = __ldg(b3v + c0), bb1 = __ldg(b3v + c0 + 1);
            const float w0  = __ldg(w4v + c0), w1  = __ldg(w4v + c0 + 1);
#pragma unroll
            for (int mt = 0; mt < 2; mt++) {
                part[mt][0] += celu_f(acc[mt][nt][0] + bb0) * w0
                             + celu_f(acc[mt][nt][1] + bb1) * w1;
                part[mt][1] += celu_f(acc[mt][nt][2] + bb0) * w0
                             + celu_f(acc[mt][nt][3] + bb1) * w1;
            }
        }
#pragma unroll
        for (int mt = 0; mt < 2; mt++)
#pragma unroll
            for (int rh = 0; rh < 2; rh++) {
                part[mt][rh] += __shfl_xor_sync(0xffffffffu, part[mt][rh], 1);
                part[mt][rh] += __shfl_xor_sync(0xffffffffu, part[mt][rh], 2);
            }
        if (tig == 0) {
            const float b4v = __ldg(b4 + t);
#pragma unroll
            for (int mt = 0; mt < 2; mt++)
#pragma unroll
                for (int rh = 0; rh < 2; rh++) {
                    const int row = wm * 32 + mt * 16 + rh * 8 + g;
                    if (row < nact) {
                        const int id = sids[row];
                        const int mol = g_is64 ? batch32[2 * id] : batch32[id];
                        atomicAdd(&out[mol], part[mt][rh] + (wn == 0 ? b4v : 0.0f));
                    }
                }
        }
    }
}

// ---------------- launch ----------------
extern "C" void kernel_launch(void* const* d_in, const int* in_sizes, int n_in,
                              void* d_out, int out_size) {
    const int*   z     = (const int*)  d_in[0];
    const float* feat  = (const float*)d_in[1];
    const int*   batch = (const int*)  d_in[2];
    const float* W1 = (const float*)d_in[4];
    const float* b1 = (const float*)d_in[5];
    const float* W2 = (const float*)d_in[6];
    const float* b2 = (const float*)d_in[7];
    const float* W3 = (const float*)d_in[8];
    const float* b3 = (const float*)d_in[9];
    const float* W4 = (const float*)d_in[10];
    const float* b4 = (const float*)d_in[11];
    float* out = (float*)d_out;

    cudaFuncSetAttribute(k_gemm1,  cudaFuncAttributeMaxDynamicSharedMemorySize, G1_SM_TOTAL);
    cudaFuncSetAttribute(k_gemm23, cudaFuncAttributeMaxDynamicSharedMemorySize, G2_SM_TOTAL);

    const int initN = (out_size > PAD_MAX) ? out_size : PAD_MAX;
    const int prepN = 5 * H1 * KPAD / 4 + 5 * H2 * H1 / 4 + 5 * H3 * H2 / 4;
    const int cpN = (prepN > N_ATOMS) ? prepN : N_ATOMS;

    k_init<<<(initN + 255) / 256, 256>>>(z, out, out_size);            // 1
    dim3 cpg((cpN + 255) / 256, 2);
    k_count_prep<<<cpg, 256>>>(z, W1, W2, W3);                         // 2
    k_scatter<<<(N_ATOMS + 255) / 256, 256>>>();                       // 3

    dim3 grid(NT_MAX, 5);
    k_gemm1<<<grid, TPB, G1_SM_TOTAL>>>(feat, b1);                     // 4 <- profiled
    k_gemm23<<<grid, TPB, G2_SM_TOTAL>>>(batch, b2, b3, W4, b4, out);  // 5
}